// round 1
// baseline (speedup 1.0000x reference)
#include <cuda_runtime.h>
#include <math.h>

// Problem constants
#define R_ 64
#define N_ 512
#define DIM_ 128
#define H_ 8
#define DH_ 64
#define INNER_ 512
#define DPAIR_ 128
#define DSW_ 16

// Scratch (device globals; no allocation allowed)
__device__ float g_q[(size_t)R_ * H_ * N_ * DH_];      // [r][h][i][d]
__device__ float g_k[(size_t)R_ * H_ * N_ * DH_];      // [r][h][j][d]
__device__ float g_v[(size_t)R_ * H_ * N_ * DH_];      // [r][h][j][d]
__device__ float g_sk[(size_t)R_ * N_ * DIM_];         // [r*N+i][c]
__device__ float g_sq[(size_t)N_ * DIM_];              // [i][c]
__device__ float g_w[(size_t)N_ * H_ * R_];            // [i][h][r]
__device__ float g_dots[(size_t)H_ * N_ * N_];         // [h][i][j]
__device__ float g_oattn[(size_t)R_ * N_ * INNER_];    // [r*N+i][h*64+d]

// ---------------------------------------------------------------------------
// Generic tiled GEMM: C = A(MxK) @ B(KxN) + bias, row-major, N==128 use-cases
// BM=128, BN=128, BK=32, 256 threads, 8x8 micro-tile
// ---------------------------------------------------------------------------
__global__ __launch_bounds__(256) void gemm_bias_kernel(
    const float* __restrict__ A, const float* __restrict__ B,
    const float* __restrict__ bias, float* __restrict__ C,
    int M, int N, int K)
{
    __shared__ float As[32][128];
    __shared__ float Bs[32][128];
    const int tid = threadIdx.x;
    const int bm = blockIdx.y * 128;
    const int bn = blockIdx.x * 128;
    const int trow = tid >> 4;
    const int tcol = tid & 15;
    float acc[8][8];
#pragma unroll
    for (int m = 0; m < 8; m++)
#pragma unroll
        for (int n = 0; n < 8; n++) acc[m][n] = 0.f;

    for (int k0 = 0; k0 < K; k0 += 32) {
#pragma unroll
        for (int t = 0; t < 4; t++) {
            int e = tid + t * 256;
            int arow = e >> 3;
            int a4 = (e & 7) * 4;
            float4 v = *(const float4*)(A + (size_t)(bm + arow) * K + k0 + a4);
            As[a4 + 0][arow] = v.x; As[a4 + 1][arow] = v.y;
            As[a4 + 2][arow] = v.z; As[a4 + 3][arow] = v.w;
        }
#pragma unroll
        for (int t = 0; t < 4; t++) {
            int e = tid + t * 256;
            int brow = e >> 5;
            int b4 = (e & 31) * 4;
            *(float4*)&Bs[brow][b4] =
                *(const float4*)(B + (size_t)(k0 + brow) * N + bn + b4);
        }
        __syncthreads();
#pragma unroll
        for (int kk = 0; kk < 32; kk++) {
            float a[8], b[8];
            *(float4*)&a[0] = *(const float4*)&As[kk][trow * 8];
            *(float4*)&a[4] = *(const float4*)&As[kk][trow * 8 + 4];
            *(float4*)&b[0] = *(const float4*)&Bs[kk][tcol * 8];
            *(float4*)&b[4] = *(const float4*)&Bs[kk][tcol * 8 + 4];
#pragma unroll
            for (int m = 0; m < 8; m++)
#pragma unroll
                for (int n = 0; n < 8; n++) acc[m][n] += a[m] * b[n];
        }
        __syncthreads();
    }
#pragma unroll
    for (int m = 0; m < 8; m++) {
        int row = bm + trow * 8 + m;
        float4 bb0 = *(const float4*)(bias + bn + tcol * 8);
        float4 bb1 = *(const float4*)(bias + bn + tcol * 8 + 4);
        float4 v0 = make_float4(acc[m][0] + bb0.x, acc[m][1] + bb0.y,
                                acc[m][2] + bb0.z, acc[m][3] + bb0.w);
        float4 v1 = make_float4(acc[m][4] + bb1.x, acc[m][5] + bb1.y,
                                acc[m][6] + bb1.z, acc[m][7] + bb1.w);
        *(float4*)(C + (size_t)row * N + bn + tcol * 8) = v0;
        *(float4*)(C + (size_t)row * N + bn + tcol * 8 + 4) = v1;
    }
}

// ---------------------------------------------------------------------------
// QKV projection with scatter into [r][h][pos][d] layout.
// A = x (32768 x 128).  Cols: [0,512)=Wq -> q, [512,1024)=Wkv[:, :512] -> k,
// [1024,1536)=Wkv[:,512:1024] -> v (i.e. col>=512 reads Wkv col-512).
// grid (12, 256)
// ---------------------------------------------------------------------------
__global__ __launch_bounds__(256) void qkv_kernel(
    const float* __restrict__ x, const float* __restrict__ Wq,
    const float* __restrict__ Wkv)
{
    __shared__ float As[32][128];
    __shared__ float Bs[32][128];
    const int tid = threadIdx.x;
    const int bx = blockIdx.x;          // 0..11 (128-col blocks)
    const int bm = blockIdx.y * 128;
    const float* Bsrc; int ldb, bcol;
    if (bx < 4) { Bsrc = Wq;  ldb = 512;  bcol = bx * 128; }
    else        { Bsrc = Wkv; ldb = 1024; bcol = bx * 128 - 512; }
    const int trow = tid >> 4;
    const int tcol = tid & 15;
    float acc[8][8];
#pragma unroll
    for (int m = 0; m < 8; m++)
#pragma unroll
        for (int n = 0; n < 8; n++) acc[m][n] = 0.f;

    for (int k0 = 0; k0 < 128; k0 += 32) {
#pragma unroll
        for (int t = 0; t < 4; t++) {
            int e = tid + t * 256;
            int arow = e >> 3;
            int a4 = (e & 7) * 4;
            float4 v = *(const float4*)(x + (size_t)(bm + arow) * 128 + k0 + a4);
            As[a4 + 0][arow] = v.x; As[a4 + 1][arow] = v.y;
            As[a4 + 2][arow] = v.z; As[a4 + 3][arow] = v.w;
        }
#pragma unroll
        for (int t = 0; t < 4; t++) {
            int e = tid + t * 256;
            int brow = e >> 5;
            int b4 = (e & 31) * 4;
            *(float4*)&Bs[brow][b4] =
                *(const float4*)(Bsrc + (size_t)(k0 + brow) * ldb + bcol + b4);
        }
        __syncthreads();
#pragma unroll
        for (int kk = 0; kk < 32; kk++) {
            float a[8], b[8];
            *(float4*)&a[0] = *(const float4*)&As[kk][trow * 8];
            *(float4*)&a[4] = *(const float4*)&As[kk][trow * 8 + 4];
            *(float4*)&b[0] = *(const float4*)&Bs[kk][tcol * 8];
            *(float4*)&b[4] = *(const float4*)&Bs[kk][tcol * 8 + 4];
#pragma unroll
            for (int m = 0; m < 8; m++)
#pragma unroll
                for (int n = 0; n < 8; n++) acc[m][n] += a[m] * b[n];
        }
        __syncthreads();
    }
    const int colbase = bx * 128 + tcol * 8;   // aligned to 8, within one head
    const int which = colbase >> 9;            // 0=q 1=k 2=v
    const int cc = colbase & 511;
    const int h = cc >> 6;
    const int d = cc & 63;
    float* dst = (which == 0) ? g_q : (which == 1) ? g_k : g_v;
#pragma unroll
    for (int m = 0; m < 8; m++) {
        int row = bm + trow * 8 + m;
        int r = row >> 9;
        int i = row & 511;
        float* p = dst + (((size_t)(r * 8 + h) * 512 + i) * 64 + d);
        *(float4*)p       = make_float4(acc[m][0], acc[m][1], acc[m][2], acc[m][3]);
        *(float4*)(p + 4) = make_float4(acc[m][4], acc[m][5], acc[m][6], acc[m][7]);
    }
}

// ---------------------------------------------------------------------------
// Row softmax weights: w[i,h,r] = softmax_r( (sq[i,h,:].sk[r,i,h,:]) / 4 )
// grid = 4096 blocks (i*8+h), 64 threads (one per r)
// ---------------------------------------------------------------------------
__global__ __launch_bounds__(64) void wsoft_kernel()
{
    const int i = blockIdx.x >> 3;
    const int h = blockIdx.x & 7;
    const int r = threadIdx.x;
    __shared__ float sm[64];
    const float* sqv = g_sq + i * 128 + h * 16;
    const float* skv = g_sk + ((size_t)r * 512 + i) * 128 + h * 16;
    float dot = 0.f;
#pragma unroll
    for (int d = 0; d < 16; d++) dot += sqv[d] * skv[d];
    float logit = dot * 0.25f;                  // / sqrt(16)
    sm[r] = logit;
    __syncthreads();
    float mx = -1e30f;
#pragma unroll 8
    for (int t = 0; t < 64; t++) mx = fmaxf(mx, sm[t]);
    __syncthreads();
    float e = __expf(logit - mx);
    sm[r] = e;
    __syncthreads();
    float sum = 0.f;
#pragma unroll 8
    for (int t = 0; t < 64; t++) sum += sm[t];
    g_w[((size_t)i * 8 + h) * 64 + r] = e / sum;
}

// ---------------------------------------------------------------------------
// Pair bias: dots[h][i][j] = LN(pair[i,j,:]) @ Wpair[:,h]  (initializes g_dots)
// One warp per (i,j).  grid(512, 64), 256 threads (8 warps)
// ---------------------------------------------------------------------------
__global__ __launch_bounds__(256) void pb_kernel(
    const float* __restrict__ pair, const float* __restrict__ ln_g,
    const float* __restrict__ ln_b, const float* __restrict__ Wpair)
{
    const int i = blockIdx.x;
    const int warp = threadIdx.x >> 5;
    const int lane = threadIdx.x & 31;
    const int j = blockIdx.y * 8 + warp;
    const float* p = pair + ((size_t)i * 512 + j) * 128;
    float xv[4];
#pragma unroll
    for (int t = 0; t < 4; t++) xv[t] = p[lane + 32 * t];
    float s  = xv[0] + xv[1] + xv[2] + xv[3];
    float s2 = xv[0]*xv[0] + xv[1]*xv[1] + xv[2]*xv[2] + xv[3]*xv[3];
#pragma unroll
    for (int o = 16; o > 0; o >>= 1) {
        s  += __shfl_xor_sync(0xffffffffu, s,  o);
        s2 += __shfl_xor_sync(0xffffffffu, s2, o);
    }
    const float mu  = s * (1.f / 128.f);
    const float var = s2 * (1.f / 128.f) - mu * mu;
    const float inv = rsqrtf(var + 1e-5f);
    float y[4];
#pragma unroll
    for (int t = 0; t < 4; t++) {
        int c = lane + 32 * t;
        y[t] = (xv[t] - mu) * inv * ln_g[c] + ln_b[c];
    }
    float accs[8];
#pragma unroll
    for (int h = 0; h < 8; h++) {
        float a = 0.f;
#pragma unroll
        for (int t = 0; t < 4; t++) {
            int c = lane + 32 * t;
            a += y[t] * Wpair[c * 8 + h];
        }
#pragma unroll
        for (int o = 16; o > 0; o >>= 1) a += __shfl_xor_sync(0xffffffffu, a, o);
        accs[h] = a;
    }
    if (lane < 8)
        g_dots[((size_t)lane * 512 + i) * 512 + j] = accs[lane];
    // note: after butterfly all lanes hold full sums, so lane==h write is valid
}

// ---------------------------------------------------------------------------
// Tied attention logits: dots[h,i,j] += scale * sum_{r,d} w[i,h,r] q[r,h,i,d] k[r,h,j,d]
// Per-h GEMM, contraction K = 4096 (r,d).  grid(4,4,8), 256 threads
// ---------------------------------------------------------------------------
__global__ __launch_bounds__(256) void dots_kernel()
{
    __shared__ float As[32][128];   // [d-chunk][i], pre-multiplied by w
    __shared__ float Bs[32][128];   // [d-chunk][j]
    const int tid = threadIdx.x;
    const int h = blockIdx.z;
    const int bi = blockIdx.y * 128;
    const int bj = blockIdx.x * 128;
    const int trow = tid >> 4;
    const int tcol = tid & 15;
    float acc[8][8];
#pragma unroll
    for (int m = 0; m < 8; m++)
#pragma unroll
        for (int n = 0; n < 8; n++) acc[m][n] = 0.f;

    for (int k0 = 0; k0 < 4096; k0 += 32) {
        const int r = k0 >> 6;
        const int doff = k0 & 63;
#pragma unroll
        for (int t = 0; t < 4; t++) {
            int e = tid + t * 256;
            int row = e >> 3;
            int a4 = (e & 7) * 4;
            int d = doff + a4;
            size_t base = (size_t)(r * 8 + h) * 512;
            float4 va = *(const float4*)(g_q + (base + bi + row) * 64 + d);
            float wv = g_w[((size_t)(bi + row) * 8 + h) * 64 + r];
            As[a4 + 0][row] = va.x * wv; As[a4 + 1][row] = va.y * wv;
            As[a4 + 2][row] = va.z * wv; As[a4 + 3][row] = va.w * wv;
            float4 vb = *(const float4*)(g_k + (base + bj + row) * 64 + d);
            Bs[a4 + 0][row] = vb.x; Bs[a4 + 1][row] = vb.y;
            Bs[a4 + 2][row] = vb.z; Bs[a4 + 3][row] = vb.w;
        }
        __syncthreads();
#pragma unroll
        for (int kk = 0; kk < 32; kk++) {
            float a[8], b[8];
            *(float4*)&a[0] = *(const float4*)&As[kk][trow * 8];
            *(float4*)&a[4] = *(const float4*)&As[kk][trow * 8 + 4];
            *(float4*)&b[0] = *(const float4*)&Bs[kk][tcol * 8];
            *(float4*)&b[4] = *(const float4*)&Bs[kk][tcol * 8 + 4];
#pragma unroll
            for (int m = 0; m < 8; m++)
#pragma unroll
                for (int n = 0; n < 8; n++) acc[m][n] += a[m] * b[n];
        }
        __syncthreads();
    }
    const float scale = 0.125f;   // dh^-0.5
#pragma unroll
    for (int m = 0; m < 8; m++) {
        int i = bi + trow * 8 + m;
        float* p = g_dots + ((size_t)h * 512 + i) * 512 + bj + tcol * 8;
        float4 o0 = *(float4*)p;
        float4 o1 = *(float4*)(p + 4);
        o0.x += acc[m][0] * scale; o0.y += acc[m][1] * scale;
        o0.z += acc[m][2] * scale; o0.w += acc[m][3] * scale;
        o1.x += acc[m][4] * scale; o1.y += acc[m][5] * scale;
        o1.z += acc[m][6] * scale; o1.w += acc[m][7] * scale;
        *(float4*)p = o0;
        *(float4*)(p + 4) = o1;
    }
}

// ---------------------------------------------------------------------------
// Softmax over j (512) per (h,i).  grid 4096, 256 threads, in-place on g_dots
// ---------------------------------------------------------------------------
__global__ __launch_bounds__(256) void softj_kernel()
{
    float* row = g_dots + (size_t)blockIdx.x * 512;
    __shared__ float red[256];
    const int t = threadIdx.x;
    float v0 = row[t], v1 = row[t + 256];
    red[t] = fmaxf(v0, v1);
    __syncthreads();
#pragma unroll
    for (int o = 128; o > 0; o >>= 1) {
        if (t < o) red[t] = fmaxf(red[t], red[t + o]);
        __syncthreads();
    }
    const float mx = red[0];
    __syncthreads();
    float e0 = __expf(v0 - mx), e1 = __expf(v1 - mx);
    red[t] = e0 + e1;
    __syncthreads();
#pragma unroll
    for (int o = 128; o > 0; o >>= 1) {
        if (t < o) red[t] = red[t] + red[t + o];
        __syncthreads();
    }
    const float inv = 1.f / red[0];
    row[t] = e0 * inv;
    row[t + 256] = e1 * inv;
}

// ---------------------------------------------------------------------------
// out_attn[r,i,h*64+d] = sum_j attn[h,i,j] v[r,h,j,d]
// Per (r,h): GEMM 512x64, K=512.  grid(4, 512=r*8+h), 256 threads, BM=128 BN=64
// ---------------------------------------------------------------------------
__global__ __launch_bounds__(256) void outv_kernel()
{
    __shared__ float As[32][128];   // attn tile [j-chunk][i]
    __shared__ float Bs[32][64];    // v tile    [j-chunk][d]
    const int tid = threadIdx.x;
    const int z = blockIdx.y;       // r*8+h
    const int h = z & 7;
    const int r = z >> 3;
    const int bi = blockIdx.x * 128;
    const int trow = tid >> 4;      // i
    const int tcol = tid & 15;      // d/4
    const float* A = g_dots + (size_t)h * 512 * 512;
    const float* B = g_v + (size_t)z * 512 * 64;
    float acc[8][4];
#pragma unroll
    for (int m = 0; m < 8; m++)
#pragma unroll
        for (int n = 0; n < 4; n++) acc[m][n] = 0.f;

    for (int k0 = 0; k0 < 512; k0 += 32) {
#pragma unroll
        for (int t = 0; t < 4; t++) {
            int e = tid + t * 256;
            int arow = e >> 3;
            int a4 = (e & 7) * 4;
            float4 v = *(const float4*)(A + (size_t)(bi + arow) * 512 + k0 + a4);
            As[a4 + 0][arow] = v.x; As[a4 + 1][arow] = v.y;
            As[a4 + 2][arow] = v.z; As[a4 + 3][arow] = v.w;
        }
#pragma unroll
        for (int t = 0; t < 2; t++) {
            int e = tid + t * 256;
            int brow = e >> 4;
            int b4 = (e & 15) * 4;
            *(float4*)&Bs[brow][b4] =
                *(const float4*)(B + (size_t)(k0 + brow) * 64 + b4);
        }
        __syncthreads();
#pragma unroll
        for (int kk = 0; kk < 32; kk++) {
            float a[8], b[4];
            *(float4*)&a[0] = *(const float4*)&As[kk][trow * 8];
            *(float4*)&a[4] = *(const float4*)&As[kk][trow * 8 + 4];
            *(float4*)&b[0] = *(const float4*)&Bs[kk][tcol * 4];
#pragma unroll
            for (int m = 0; m < 8; m++)
#pragma unroll
                for (int n = 0; n < 4; n++) acc[m][n] += a[m] * b[n];
        }
        __syncthreads();
    }
#pragma unroll
    for (int m = 0; m < 8; m++) {
        int i = bi + trow * 8 + m;
        float* p = g_oattn + ((size_t)(r * 512 + i)) * 512 + h * 64 + tcol * 4;
        *(float4*)p = make_float4(acc[m][0], acc[m][1], acc[m][2], acc[m][3]);
    }
}

// ---------------------------------------------------------------------------
extern "C" void kernel_launch(void* const* d_in, const int* in_sizes, int n_in,
                              void* d_out, int out_size)
{
    const float* x     = (const float*)d_in[0];
    const float* pair  = (const float*)d_in[1];
    const float* Wq    = (const float*)d_in[2];
    const float* Wkv   = (const float*)d_in[3];
    const float* Wo    = (const float*)d_in[4];
    const float* bo    = (const float*)d_in[5];
    const float* ln_g  = (const float*)d_in[6];
    const float* ln_b  = (const float*)d_in[7];
    const float* Wpair = (const float*)d_in[8];
    const float* Wsq   = (const float*)d_in[9];
    const float* bsq   = (const float*)d_in[10];
    const float* Wsk   = (const float*)d_in[11];
    const float* bsk   = (const float*)d_in[12];
    float* out = (float*)d_out;

    float *p_sk = nullptr, *p_sq = nullptr, *p_oattn = nullptr;
    cudaGetSymbolAddress((void**)&p_sk, g_sk);
    cudaGetSymbolAddress((void**)&p_sq, g_sq);
    cudaGetSymbolAddress((void**)&p_oattn, g_oattn);

    // 1. QKV projection (scattered into per-head layouts)
    qkv_kernel<<<dim3(12, 256), 256>>>(x, Wq, Wkv);
    // 2. sk = x @ Wsk + bsk  (all 32768 rows)
    gemm_bias_kernel<<<dim3(1, 256), 256>>>(x, Wsk, bsk, p_sk, 32768, 128, 128);
    // 3. sq = x[r=0] @ Wsq + bsq (first 512 rows of x)
    gemm_bias_kernel<<<dim3(1, 4), 256>>>(x, Wsq, bsq, p_sq, 512, 128, 128);
    // 4. soft tied-row weights
    wsoft_kernel<<<4096, 64>>>();
    // 5. pair bias (initializes g_dots)
    pb_kernel<<<dim3(512, 64), 256>>>(pair, ln_g, ln_b, Wpair);
    // 6. tied logits accumulate into g_dots
    dots_kernel<<<dim3(4, 4, 8), 256>>>();
    // 7. softmax over j
    softj_kernel<<<4096, 256>>>();
    // 8. attn @ v
    outv_kernel<<<dim3(4, 512), 256>>>();
    // 9. output projection
    gemm_bias_kernel<<<dim3(1, 256), 256>>>(p_oattn, Wo, bo, out, 32768, 128, 512);
}

// round 2
// speedup vs baseline: 2.8912x; 2.8912x over previous
#include <cuda_runtime.h>
#include <cuda_fp16.h>
#include <math.h>

// Problem constants
#define R_ 64
#define N_ 512
#define DIM_ 128
#define H_ 8
#define DH_ 64
#define INNER_ 512
#define DPAIR_ 128

// ---------------------------------------------------------------------------
// Device scratch (no allocation allowed)
// ---------------------------------------------------------------------------
__device__ __half g_xh[(size_t)32768 * 128];            // x in fp16
__device__ __half g_WT[(size_t)1664 * 128];             // fused [Wq|Wk|Wv|Wsk]^T, [n][k]
__device__ __half g_WsqT[(size_t)128 * 128];            // Wsq^T [n][k]
__device__ __half g_WoT[(size_t)128 * 512];             // Wo^T [n][k]
__device__ float  g_bias1664[1664];                     // 0...0 | bsk
__device__ __half g_proj[(size_t)32768 * 1664];         // [(r,i)][q|k|v|sk]
__device__ __half g_sqh[(size_t)512 * 128];             // sq
__device__ float  g_w[(size_t)512 * 8 * 64];            // [i][h][r]
__device__ float  g_dots[(size_t)8 * 512 * 512];        // [h][i][j]
__device__ __half g_Awq[(size_t)8 * 512 * 4096];        // [h][i][(r,d)]  (w-premult q)
__device__ __half g_Bk[(size_t)8 * 512 * 4096];         // [h][j][(r,d)]
__device__ __half g_Bv[(size_t)512 * 64 * 512];         // [(r,h)][d][j]  (v transposed)
__device__ __half g_attnh[(size_t)8 * 512 * 512];       // softmax(dots) fp16
__device__ __half g_oattnh[(size_t)32768 * 512];        // [(r,i)][h*64+d]

// ---------------------------------------------------------------------------
// PTX helpers
// ---------------------------------------------------------------------------
__device__ __forceinline__ unsigned smaddr(const void* p) {
    return (unsigned)__cvta_generic_to_shared(p);
}
__device__ __forceinline__ void ldsm4(unsigned& r0, unsigned& r1, unsigned& r2,
                                      unsigned& r3, unsigned addr) {
    asm volatile("ldmatrix.sync.aligned.m8n8.x4.shared.b16 {%0,%1,%2,%3},[%4];\n"
                 : "=r"(r0), "=r"(r1), "=r"(r2), "=r"(r3) : "r"(addr));
}
__device__ __forceinline__ void mma16816(float* c, const unsigned* a, const unsigned* b) {
    asm volatile(
        "mma.sync.aligned.m16n8k16.row.col.f32.f16.f16.f32 "
        "{%0,%1,%2,%3},{%4,%5,%6,%7},{%8,%9},{%0,%1,%2,%3};\n"
        : "+f"(c[0]), "+f"(c[1]), "+f"(c[2]), "+f"(c[3])
        : "r"(a[0]), "r"(a[1]), "r"(a[2]), "r"(a[3]), "r"(b[0]), "r"(b[1]));
}
__device__ __forceinline__ void cpa16(void* s, const void* g) {
    asm volatile("cp.async.cg.shared.global [%0],[%1],16;\n"
                 :: "r"(smaddr(s)), "l"(g));
}
__device__ __forceinline__ void cpcommit() { asm volatile("cp.async.commit_group;\n"); }
template <int NN> __device__ __forceinline__ void cpwait() {
    asm volatile("cp.async.wait_group %0;\n" :: "n"(NN));
}

// ---------------------------------------------------------------------------
// Generic NT tensor-core GEMM:  C(M,N) (+)= A(M,K) @ B(N,K)^T  (both K-major fp16)
// BM=128, BK=32, 256 threads, warps 2x4, warp tile 64 x (BN/4).
// OUTM: 0 = Cf += alpha*acc (fp32 RMW)   1 = Ch = half(acc + bias)
//       2 = Cf = acc + bias (fp32)
// ZMODE: 0: Az=A+z*zsA, Bz=B+z*zsB, coff=z*zsC
//        1: Az=A+(z&7)*zsA, Bz=B+z*zsB, coff=(z>>3)*zsC+(z&7)*64
// ---------------------------------------------------------------------------
template <int BN, int OUTM, int ZMODE>
__global__ __launch_bounds__(256) void mma_nt(
    const __half* __restrict__ A, const __half* __restrict__ B,
    float* __restrict__ Cf, __half* __restrict__ Ch,
    const float* __restrict__ bias,
    int K, int ldA, int ldB, int ldC,
    long zsA, long zsB, long zsC, float alpha)
{
    constexpr int BM = 128, BK = 32, SK = 40;
    constexpr int WN = BN / 4;     // 32 or 16
    constexpr int NT = WN / 8;     // 4 or 2
    __shared__ __half As[2][BM * SK];
    __shared__ __half Bs[2][BN * SK];

    const int tid = threadIdx.x, warp = tid >> 5, lane = tid & 31;
    const int z = blockIdx.z;
    const __half* Az; const __half* Bz; long coff;
    if (ZMODE == 0) { Az = A + (long)z * zsA; Bz = B + (long)z * zsB; coff = (long)z * zsC; }
    else            { Az = A + (long)(z & 7) * zsA; Bz = B + (long)z * zsB;
                      coff = (long)(z >> 3) * zsC + (long)(z & 7) * 64; }
    const int bm = blockIdx.y * BM, bn = blockIdx.x * BN;
    const int wm = (warp >> 2) * 64, wn = (warp & 3) * WN;

    float acc[4][NT][4];
#pragma unroll
    for (int a = 0; a < 4; a++)
#pragma unroll
        for (int b = 0; b < NT; b++)
#pragma unroll
            for (int c = 0; c < 4; c++) acc[a][b][c] = 0.f;

    const int arow = tid >> 1, acol = (tid & 1) * 16;
    const int brow = tid >> 2, bcol = (tid & 3) * 8;

    const int nIter = K / BK;
    auto issue = [&](int it, int buf) {
        const int k0 = it * BK;
        const __half* ap = Az + (size_t)(bm + arow) * ldA + k0 + acol;
        cpa16(&As[buf][arow * SK + acol], ap);
        cpa16(&As[buf][arow * SK + acol + 8], ap + 8);
        if (BN == 128) {
            const __half* bp = Bz + (size_t)(bn + arow) * ldB + k0 + acol;
            cpa16(&Bs[buf][arow * SK + acol], bp);
            cpa16(&Bs[buf][arow * SK + acol + 8], bp + 8);
        } else {
            cpa16(&Bs[buf][brow * SK + bcol],
                  Bz + (size_t)(bn + brow) * ldB + k0 + bcol);
        }
    };

    issue(0, 0);
    cpcommit();

    for (int it = 0; it < nIter; ++it) {
        const int buf = it & 1;
        if (it + 1 < nIter) issue(it + 1, buf ^ 1);
        cpcommit();
        cpwait<1>();
        __syncthreads();

        const unsigned abase = smaddr(&As[buf][0]);
        const unsigned bbase = smaddr(&Bs[buf][0]);
#pragma unroll
        for (int ks = 0; ks < 2; ++ks) {
            unsigned af[4][4];
#pragma unroll
            for (int tm = 0; tm < 4; tm++) {
                int row = wm + tm * 16 + (lane & 7) + ((lane >> 3) & 1) * 8;
                int col = ks * 16 + (lane >> 4) * 8;
                ldsm4(af[tm][0], af[tm][1], af[tm][2], af[tm][3],
                      abase + (unsigned)(row * SK + col) * 2u);
            }
            unsigned bf[NT][2];
#pragma unroll
            for (int p = 0; p < NT / 2; p++) {
                int row = wn + p * 16 + (lane & 7) + ((lane >> 4) & 1) * 8;
                int col = ks * 16 + ((lane >> 3) & 1) * 8;
                unsigned r0, r1, r2, r3;
                ldsm4(r0, r1, r2, r3, bbase + (unsigned)(row * SK + col) * 2u);
                bf[2 * p][0] = r0; bf[2 * p][1] = r1;
                bf[2 * p + 1][0] = r2; bf[2 * p + 1][1] = r3;
            }
#pragma unroll
            for (int tm = 0; tm < 4; tm++)
#pragma unroll
                for (int tn = 0; tn < NT; tn++)
                    mma16816(acc[tm][tn], af[tm], bf[tn]);
        }
        __syncthreads();
    }

    // epilogue
#pragma unroll
    for (int tm = 0; tm < 4; tm++) {
#pragma unroll
        for (int tn = 0; tn < NT; tn++) {
            int row0 = bm + wm + tm * 16 + (lane >> 2);
            int col = bn + wn + tn * 8 + (lane & 3) * 2;
#pragma unroll
            for (int half_ : {0, 1}) {
                int row = row0 + half_ * 8;
                float v0 = acc[tm][tn][half_ * 2 + 0];
                float v1 = acc[tm][tn][half_ * 2 + 1];
                if (OUTM == 0) {
                    float* p = Cf + coff + (size_t)row * ldC + col;
                    float2 o = *(float2*)p;
                    o.x += alpha * v0; o.y += alpha * v1;
                    *(float2*)p = o;
                } else if (OUTM == 1) {
                    float b0 = bias[col], b1 = bias[col + 1];
                    *(__half2*)(Ch + coff + (size_t)row * ldC + col) =
                        __floats2half2_rn(v0 + b0, v1 + b1);
                } else {
                    float b0 = bias[col], b1 = bias[col + 1];
                    float2 o = make_float2(v0 + b0, v1 + b1);
                    *(float2*)(Cf + coff + (size_t)row * ldC + col) = o;
                }
            }
        }
    }
}

// ---------------------------------------------------------------------------
// Prep: convert x to fp16
// ---------------------------------------------------------------------------
__global__ __launch_bounds__(256) void cvt_x_kernel(const float* __restrict__ x)
{
    size_t i = (size_t)blockIdx.x * 256 + threadIdx.x;   // float4 index
    float4 v = *(const float4*)(x + i * 4);
    __half2* d = (__half2*)(g_xh + i * 4);
    d[0] = __floats2half2_rn(v.x, v.y);
    d[1] = __floats2half2_rn(v.z, v.w);
}

// Build transposed fp16 weights + fused bias
__global__ __launch_bounds__(256) void build_wb_kernel(
    const float* __restrict__ Wq, const float* __restrict__ Wkv,
    const float* __restrict__ Wsk, const float* __restrict__ Wsq,
    const float* __restrict__ Wo, const float* __restrict__ bsk)
{
    int i = blockIdx.x * 256 + threadIdx.x;
    if (i < 1664 * 128) {
        int n = i >> 7, k = i & 127;
        float v;
        if (n < 512) v = Wq[k * 512 + n];
        else if (n < 1536) v = Wkv[k * 1024 + (n - 512)];
        else v = Wsk[k * 128 + (n - 1536)];
        g_WT[(size_t)n * 128 + k] = __float2half(v);
    }
    if (i < 128 * 128) {
        int n = i >> 7, k = i & 127;
        g_WsqT[(size_t)n * 128 + k] = __float2half(Wsq[k * 128 + n]);
    }
    if (i < 128 * 512) {
        int n = i >> 9, k = i & 511;
        g_WoT[(size_t)n * 512 + k] = __float2half(Wo[k * 128 + n]);
    }
    if (i < 1664) g_bias1664[i] = (i < 1536) ? 0.f : bsk[i - 1536];
}

// ---------------------------------------------------------------------------
// Row softmax weights: w[i,h,r] = softmax_r( sq[i,h,:].sk[r,i,h,:] / 4 )
// 256 threads = 4 (i,h) groups of 64 (one per r)
// ---------------------------------------------------------------------------
__global__ __launch_bounds__(256) void wsoft_kernel()
{
    const int g = threadIdx.x >> 6, r = threadIdx.x & 63;
    const int ih = blockIdx.x * 4 + g;         // i*8+h
    const int i = ih >> 3, h = ih & 7;
    __shared__ float sm[4][64];
    const __half* sqv = g_sqh + (size_t)i * 128 + h * 16;
    const __half* skv = g_proj + ((size_t)(r * 512 + i)) * 1664 + 1536 + h * 16;
    float dot = 0.f;
#pragma unroll
    for (int d = 0; d < 16; d++)
        dot += __half2float(sqv[d]) * __half2float(skv[d]);
    float logit = dot * 0.25f;
    sm[g][r] = logit;
    __syncthreads();
    float mx = -1e30f;
#pragma unroll 8
    for (int t = 0; t < 64; t++) mx = fmaxf(mx, sm[g][t]);
    __syncthreads();
    float e = __expf(logit - mx);
    sm[g][r] = e;
    __syncthreads();
    float sum = 0.f;
#pragma unroll 8
    for (int t = 0; t < 64; t++) sum += sm[g][t];
    g_w[(size_t)ih * 64 + r] = e / sum;
}

// ---------------------------------------------------------------------------
// Build dots operands: A = w*q  -> [h][i][(r,d)],  B = k -> [h][j][(r,d)]
// ---------------------------------------------------------------------------
__global__ __launch_bounds__(256) void prep_ab_kernel()
{
    unsigned u = blockIdx.x * 256 + threadIdx.x;  // (h,i,r,dseg)
    int dseg = u & 7;
    int r = (u >> 3) & 63;
    int i = (u >> 9) & 511;
    int h = u >> 18;
    size_t src = ((size_t)(r * 512 + i)) * 1664 + h * 64 + dseg * 8;
    uint4 qv = *(const uint4*)(g_proj + src);
    float w = g_w[((size_t)i * 8 + h) * 64 + r];
    __half2* hp = (__half2*)&qv;
#pragma unroll
    for (int t = 0; t < 4; t++) {
        float2 f = __half22float2(hp[t]);
        hp[t] = __floats2half2_rn(f.x * w, f.y * w);
    }
    size_t dst = ((size_t)(h * 512 + i)) * 4096 + r * 64 + dseg * 8;
    *(uint4*)(g_Awq + dst) = qv;
    *(uint4*)(g_Bk + dst) = *(const uint4*)(g_proj + src + 512);
}

// ---------------------------------------------------------------------------
// v transpose: g_Bv[(r,h)][d][j] from g_proj v columns.  grid (4 jtiles, 512 z)
// ---------------------------------------------------------------------------
__global__ __launch_bounds__(256) void vtrans_kernel()
{
    const int jt = blockIdx.x, z = blockIdx.y;
    const int r = z >> 3, h = z & 7;
    __shared__ __half ts[128][72];
    const int tid = threadIdx.x;
#pragma unroll
    for (int p = 0; p < 4; p++) {
        int u = tid + p * 256;
        int j = u >> 3, dseg = u & 7;
        uint4 v = *(const uint4*)(g_proj +
            ((size_t)(r * 512 + jt * 128 + j)) * 1664 + 1024 + h * 64 + dseg * 8);
        *(uint4*)&ts[j][dseg * 8] = v;
    }
    __syncthreads();
#pragma unroll
    for (int p = 0; p < 4; p++) {
        int u = tid + p * 256;
        int d = u & 63, jseg = u >> 6;
        __half tmp[8];
#pragma unroll
        for (int jj = 0; jj < 8; jj++) tmp[jj] = ts[jseg * 8 + jj][d];
        *(uint4*)(g_Bv + (size_t)z * 32768 + (size_t)d * 512 + jt * 128 + jseg * 8) =
            *(uint4*)tmp;
    }
}

// ---------------------------------------------------------------------------
// Pair bias: dots[h][i][j] = LN(pair[i,j,:]) @ Wpair[:,h]  (initializes g_dots)
// ---------------------------------------------------------------------------
__global__ __launch_bounds__(256) void pb_kernel(
    const float* __restrict__ pair, const float* __restrict__ ln_g,
    const float* __restrict__ ln_b, const float* __restrict__ Wpair)
{
    const int i = blockIdx.x;
    const int warp = threadIdx.x >> 5;
    const int lane = threadIdx.x & 31;
    const int j = blockIdx.y * 8 + warp;
    const float* p = pair + ((size_t)i * 512 + j) * 128;
    float xv[4];
#pragma unroll
    for (int t = 0; t < 4; t++) xv[t] = p[lane + 32 * t];
    float s  = xv[0] + xv[1] + xv[2] + xv[3];
    float s2 = xv[0]*xv[0] + xv[1]*xv[1] + xv[2]*xv[2] + xv[3]*xv[3];
#pragma unroll
    for (int o = 16; o > 0; o >>= 1) {
        s  += __shfl_xor_sync(0xffffffffu, s,  o);
        s2 += __shfl_xor_sync(0xffffffffu, s2, o);
    }
    const float mu  = s * (1.f / 128.f);
    const float var = s2 * (1.f / 128.f) - mu * mu;
    const float inv = rsqrtf(var + 1e-5f);
    float y[4];
#pragma unroll
    for (int t = 0; t < 4; t++) {
        int c = lane + 32 * t;
        y[t] = (xv[t] - mu) * inv * ln_g[c] + ln_b[c];
    }
    float accs[8];
#pragma unroll
    for (int h = 0; h < 8; h++) {
        float a = 0.f;
#pragma unroll
        for (int t = 0; t < 4; t++) {
            int c = lane + 32 * t;
            a += y[t] * Wpair[c * 8 + h];
        }
#pragma unroll
        for (int o = 16; o > 0; o >>= 1) a += __shfl_xor_sync(0xffffffffu, a, o);
        accs[h] = a;
    }
    if (lane < 8)
        g_dots[((size_t)lane * 512 + i) * 512 + j] = accs[lane];
}

// ---------------------------------------------------------------------------
// Softmax over j, write fp16 attn
// ---------------------------------------------------------------------------
__global__ __launch_bounds__(256) void softj_kernel()
{
    const float* row = g_dots + (size_t)blockIdx.x * 512;
    __half* orow = g_attnh + (size_t)blockIdx.x * 512;
    __shared__ float red[256];
    const int t = threadIdx.x;
    float v0 = row[t], v1 = row[t + 256];
    red[t] = fmaxf(v0, v1);
    __syncthreads();
#pragma unroll
    for (int o = 128; o > 0; o >>= 1) {
        if (t < o) red[t] = fmaxf(red[t], red[t + o]);
        __syncthreads();
    }
    const float mx = red[0];
    __syncthreads();
    float e0 = __expf(v0 - mx), e1 = __expf(v1 - mx);
    red[t] = e0 + e1;
    __syncthreads();
#pragma unroll
    for (int o = 128; o > 0; o >>= 1) {
        if (t < o) red[t] = red[t] + red[t + o];
        __syncthreads();
    }
    const float inv = 1.f / red[0];
    orow[t] = __float2half(e0 * inv);
    orow[t + 256] = __float2half(e1 * inv);
}

// ---------------------------------------------------------------------------
extern "C" void kernel_launch(void* const* d_in, const int* in_sizes, int n_in,
                              void* d_out, int out_size)
{
    const float* x     = (const float*)d_in[0];
    const float* pair  = (const float*)d_in[1];
    const float* Wq    = (const float*)d_in[2];
    const float* Wkv   = (const float*)d_in[3];
    const float* Wo    = (const float*)d_in[4];
    const float* bo    = (const float*)d_in[5];
    const float* ln_g  = (const float*)d_in[6];
    const float* ln_b  = (const float*)d_in[7];
    const float* Wpair = (const float*)d_in[8];
    const float* Wsq   = (const float*)d_in[9];
    const float* bsq   = (const float*)d_in[10];
    const float* Wsk   = (const float*)d_in[11];
    const float* bsk   = (const float*)d_in[12];
    float* out = (float*)d_out;

    __half *p_xh, *p_WT, *p_WsqT, *p_WoT, *p_proj, *p_sqh, *p_Awq, *p_Bk, *p_Bv,
           *p_attnh, *p_oattnh;
    float *p_bias1664, *p_dots;
    cudaGetSymbolAddress((void**)&p_xh, g_xh);
    cudaGetSymbolAddress((void**)&p_WT, g_WT);
    cudaGetSymbolAddress((void**)&p_WsqT, g_WsqT);
    cudaGetSymbolAddress((void**)&p_WoT, g_WoT);
    cudaGetSymbolAddress((void**)&p_proj, g_proj);
    cudaGetSymbolAddress((void**)&p_sqh, g_sqh);
    cudaGetSymbolAddress((void**)&p_Awq, g_Awq);
    cudaGetSymbolAddress((void**)&p_Bk, g_Bk);
    cudaGetSymbolAddress((void**)&p_Bv, g_Bv);
    cudaGetSymbolAddress((void**)&p_attnh, g_attnh);
    cudaGetSymbolAddress((void**)&p_oattnh, g_oattnh);
    cudaGetSymbolAddress((void**)&p_bias1664, g_bias1664);
    cudaGetSymbolAddress((void**)&p_dots, g_dots);

    // prep
    build_wb_kernel<<<832, 256>>>(Wq, Wkv, Wsk, Wsq, Wo, bsk);
    cvt_x_kernel<<<4096, 256>>>(x);
    // pair bias (fp32) -> g_dots
    pb_kernel<<<dim3(512, 64), 256>>>(pair, ln_g, ln_b, Wpair);
    // fused projection: [q|k|v|sk] = x @ WT^T  (M=32768, N=1664, K=128)
    mma_nt<128, 1, 0><<<dim3(13, 256, 1), 256>>>(
        p_xh, p_WT, nullptr, p_proj, p_bias1664, 128, 128, 128, 1664, 0, 0, 0, 1.f);
    // sq = x[:512] @ Wsq^T + bsq
    mma_nt<128, 1, 0><<<dim3(1, 4, 1), 256>>>(
        p_xh, p_WsqT, nullptr, p_sqh, bsq, 128, 128, 128, 128, 0, 0, 0, 1.f);
    // tied-row softmax weights
    wsoft_kernel<<<1024, 256>>>();
    // dots operands (w*q scatter, k scatter)
    prep_ab_kernel<<<8192, 256>>>();
    // v transpose
    vtrans_kernel<<<dim3(4, 512), 256>>>();
    // dots += 0.125 * (wq) @ k^T   per head (M=512, N=512, K=4096, Z=8)
    mma_nt<128, 0, 0><<<dim3(4, 4, 8), 256>>>(
        p_Awq, p_Bk, p_dots, nullptr, nullptr, 4096, 4096, 4096, 512,
        (long)512 * 4096, (long)512 * 4096, (long)512 * 512, 0.125f);
    // softmax over j -> fp16 attn
    softj_kernel<<<4096, 256>>>();
    // out_attn = attn @ v   (M=512, N=64, K=512, Z=512 (r,h))
    mma_nt<64, 1, 1><<<dim3(1, 4, 512), 256>>>(
        p_attnh, p_Bv, nullptr, p_oattnh, p_bias1664, 512, 512, 512, 512,
        (long)512 * 512, (long)64 * 512, (long)512 * 512, 1.f);
    // final: out = oattn @ Wo^T + bo  (M=32768, N=128, K=512)
    mma_nt<128, 2, 0><<<dim3(1, 256, 1), 256>>>(
        p_oattnh, p_WoT, out, nullptr, bo, 512, 512, 512, 128, 0, 0, 0, 1.f);
}

// round 6
// speedup vs baseline: 3.0824x; 1.0662x over previous
#include <cuda_runtime.h>
#include <cuda_fp16.h>
#include <math.h>

// Problem constants
#define R_ 64
#define N_ 512
#define DIM_ 128
#define H_ 8
#define DH_ 64
#define INNER_ 512
#define DPAIR_ 128

// ---------------------------------------------------------------------------
// Device scratch (no allocation allowed)
// ---------------------------------------------------------------------------
__device__ __half g_xh[(size_t)32768 * 128];            // x in fp16
__device__ __half g_WT[(size_t)1664 * 128];             // fused [Wq|Wk|Wv|Wsk]^T, [n][k]
__device__ __half g_WsqT[(size_t)128 * 128];            // Wsq^T [n][k]
__device__ __half g_WoT[(size_t)128 * 512];             // Wo^T [n][k]
__device__ float  g_bias1664[1664];                     // 0...0 | bsk
__device__ __half g_proj[(size_t)32768 * 1664];         // [(r,i)][q|k|v|sk]
__device__ __half g_sqh[(size_t)512 * 128];             // sq
__device__ float  g_w[(size_t)512 * 8 * 64];            // [i][h][r]
__device__ float  g_dots[(size_t)8 * 512 * 512];        // [h][i][j]   (pair bias)
__device__ float  g_dots4[(size_t)4 * 8 * 512 * 512];   // K-split partials
__device__ __half g_Awq[(size_t)8 * 512 * 4096];        // [h][i][(r,d)]  (w-premult q)
__device__ __half g_Bk[(size_t)8 * 512 * 4096];         // [h][j][(r,d)]
__device__ __half g_Bv[(size_t)8 * 4096 * 512];         // [h][(r,d)][j]  (v transposed)
__device__ __half g_attnh[(size_t)8 * 512 * 512];       // softmax(dots) fp16
__device__ __half g_oattnh[(size_t)32768 * 512];        // [(r,i)][h*64+d]

#define DOTS_SLICE ((size_t)8 * 512 * 512)

// ---------------------------------------------------------------------------
// PTX helpers
// ---------------------------------------------------------------------------
__device__ __forceinline__ unsigned smaddr(const void* p) {
    return (unsigned)__cvta_generic_to_shared(p);
}
__device__ __forceinline__ void ldsm4(unsigned& r0, unsigned& r1, unsigned& r2,
                                      unsigned& r3, unsigned addr) {
    asm volatile("ldmatrix.sync.aligned.m8n8.x4.shared.b16 {%0,%1,%2,%3},[%4];\n"
                 : "=r"(r0), "=r"(r1), "=r"(r2), "=r"(r3) : "r"(addr));
}
__device__ __forceinline__ void mma16816(float* c, const unsigned* a, const unsigned* b) {
    asm volatile(
        "mma.sync.aligned.m16n8k16.row.col.f32.f16.f16.f32 "
        "{%0,%1,%2,%3},{%4,%5,%6,%7},{%8,%9},{%0,%1,%2,%3};\n"
        : "+f"(c[0]), "+f"(c[1]), "+f"(c[2]), "+f"(c[3])
        : "r"(a[0]), "r"(a[1]), "r"(a[2]), "r"(a[3]), "r"(b[0]), "r"(b[1]));
}
__device__ __forceinline__ void cpa16(void* s, const void* g) {
    asm volatile("cp.async.cg.shared.global [%0],[%1],16;\n"
                 :: "r"(smaddr(s)), "l"(g));
}
__device__ __forceinline__ void cpcommit() { asm volatile("cp.async.commit_group;\n"); }
template <int NN> __device__ __forceinline__ void cpwait() {
    asm volatile("cp.async.wait_group %0;\n" :: "n"(NN));
}

// ---------------------------------------------------------------------------
// NT tensor-core GEMM:  C(M,N) (+)= A(M,K) @ B(N,K)^T  (both K-major fp16)
// BM=128, BN=128, BK=32, 3-stage cp.async pipeline, 256 threads,
// warps 2x4, warp tile 64x32.
// OUTM: 1 = Ch = half(acc + bias)
//       2 = Cf = acc + bias (fp32)
//       3 = Cf = alpha*acc (fp32 plain store; K-split partials)
//       4 = attn@v scatter: Ch[((col>>6)*512+row)*512 + z*64 + (col&63)]
// ZMODE: 0: Az=A+z*zsA, Bz=B+z*zsB, coff=z*zsC
//        2: h=z&7, ks=z>>3: Az=A+h*zsA+ks*1024, Bz=B+h*zsB+ks*1024,
//           coff=(ks*8+h)*zsC
// ---------------------------------------------------------------------------
template <int OUTM, int ZMODE>
__global__ __launch_bounds__(256) void mma_nt(
    const __half* __restrict__ A, const __half* __restrict__ B,
    float* __restrict__ Cf, __half* __restrict__ Ch,
    const float* __restrict__ bias,
    int K, int ldA, int ldB, int ldC,
    long zsA, long zsB, long zsC, float alpha)
{
    constexpr int BM = 128, BN = 128, BK = 32, SK = 40;
    constexpr int NT = 4;          // 32/8
    extern __shared__ __half sh[];
    __half* Asm = sh;                        // [3][BM*SK]
    __half* Bsm = sh + 3 * BM * SK;          // [3][BN*SK]

    const int tid = threadIdx.x, warp = tid >> 5, lane = tid & 31;
    const int z = blockIdx.z;
    const __half* Az; const __half* Bz; long coff;
    if (ZMODE == 0) {
        Az = A + (long)z * zsA; Bz = B + (long)z * zsB; coff = (long)z * zsC;
    } else {
        int h = z & 7, ks = z >> 3;
        Az = A + (long)h * zsA + ks * 1024;
        Bz = B + (long)h * zsB + ks * 1024;
        coff = (long)(ks * 8 + h) * zsC;
    }
    const int bm = blockIdx.y * BM, bn = blockIdx.x * BN;
    const int wm = (warp >> 2) * 64, wn = (warp & 3) * 32;

    float acc[4][NT][4];
#pragma unroll
    for (int a = 0; a < 4; a++)
#pragma unroll
        for (int b = 0; b < NT; b++)
#pragma unroll
            for (int c = 0; c < 4; c++) acc[a][b][c] = 0.f;

    const int arow = tid >> 1, acol = (tid & 1) * 16;
    const int nIter = K / BK;

    auto issue = [&](int it, int buf) {
        const int k0 = it * BK;
        __half* as = Asm + buf * (BM * SK);
        __half* bs = Bsm + buf * (BN * SK);
        const __half* ap = Az + (size_t)(bm + arow) * ldA + k0 + acol;
        cpa16(&as[arow * SK + acol], ap);
        cpa16(&as[arow * SK + acol + 8], ap + 8);
        const __half* bp = Bz + (size_t)(bn + arow) * ldB + k0 + acol;
        cpa16(&bs[arow * SK + acol], bp);
        cpa16(&bs[arow * SK + acol + 8], bp + 8);
    };

    issue(0, 0); cpcommit();
    if (nIter > 1) issue(1, 1);
    cpcommit();

    for (int it = 0; it < nIter; ++it) {
        cpwait<1>();
        __syncthreads();
        if (it + 2 < nIter) issue(it + 2, (it + 2) % 3);
        cpcommit();

        const int buf = it % 3;
        const unsigned abase = smaddr(Asm + buf * (BM * SK));
        const unsigned bbase = smaddr(Bsm + buf * (BN * SK));
#pragma unroll
        for (int ks = 0; ks < 2; ++ks) {
            unsigned af[4][4];
#pragma unroll
            for (int tm = 0; tm < 4; tm++) {
                int row = wm + tm * 16 + (lane & 7) + ((lane >> 3) & 1) * 8;
                int col = ks * 16 + (lane >> 4) * 8;
                ldsm4(af[tm][0], af[tm][1], af[tm][2], af[tm][3],
                      abase + (unsigned)(row * SK + col) * 2u);
            }
            unsigned bf[NT][2];
#pragma unroll
            for (int p = 0; p < NT / 2; p++) {
                int row = wn + p * 16 + (lane & 7) + ((lane >> 4) & 1) * 8;
                int col = ks * 16 + ((lane >> 3) & 1) * 8;
                unsigned r0, r1, r2, r3;
                ldsm4(r0, r1, r2, r3, bbase + (unsigned)(row * SK + col) * 2u);
                bf[2 * p][0] = r0; bf[2 * p][1] = r1;
                bf[2 * p + 1][0] = r2; bf[2 * p + 1][1] = r3;
            }
#pragma unroll
            for (int tm = 0; tm < 4; tm++)
#pragma unroll
                for (int tn = 0; tn < NT; tn++)
                    mma16816(acc[tm][tn], af[tm], bf[tn]);
        }
    }

    // epilogue
#pragma unroll
    for (int tm = 0; tm < 4; tm++) {
#pragma unroll
        for (int tn = 0; tn < NT; tn++) {
            int row0 = bm + wm + tm * 16 + (lane >> 2);
            int col = bn + wn + tn * 8 + (lane & 3) * 2;
#pragma unroll
            for (int half_ : {0, 1}) {
                int row = row0 + half_ * 8;
                float v0 = acc[tm][tn][half_ * 2 + 0];
                float v1 = acc[tm][tn][half_ * 2 + 1];
                if (OUTM == 1) {
                    float b0 = bias[col], b1 = bias[col + 1];
                    *(__half2*)(Ch + coff + (size_t)row * ldC + col) =
                        __floats2half2_rn(v0 + b0, v1 + b1);
                } else if (OUTM == 2) {
                    float b0 = bias[col], b1 = bias[col + 1];
                    float2 o = make_float2(v0 + b0, v1 + b1);
                    *(float2*)(Cf + coff + (size_t)row * ldC + col) = o;
                } else if (OUTM == 3) {
                    float2 o = make_float2(alpha * v0, alpha * v1);
                    *(float2*)(Cf + coff + (size_t)row * ldC + col) = o;
                } else {
                    size_t addr = ((size_t)((col >> 6) * 512 + row)) * 512
                                  + z * 64 + (col & 63);
                    *(__half2*)(Ch + addr) = __floats2half2_rn(v0, v1);
                }
            }
        }
    }
}

// ---------------------------------------------------------------------------
// Prep: convert x to fp16
// ---------------------------------------------------------------------------
__global__ __launch_bounds__(256) void cvt_x_kernel(const float* __restrict__ x)
{
    size_t i = (size_t)blockIdx.x * 256 + threadIdx.x;   // float4 index
    float4 v = *(const float4*)(x + i * 4);
    __half2* d = (__half2*)(g_xh + i * 4);
    d[0] = __floats2half2_rn(v.x, v.y);
    d[1] = __floats2half2_rn(v.z, v.w);
}

// Build transposed fp16 weights + fused bias
__global__ __launch_bounds__(256) void build_wb_kernel(
    const float* __restrict__ Wq, const float* __restrict__ Wkv,
    const float* __restrict__ Wsk, const float* __restrict__ Wsq,
    const float* __restrict__ Wo, const float* __restrict__ bsk)
{
    int i = blockIdx.x * 256 + threadIdx.x;
    if (i < 1664 * 128) {
        int n = i >> 7, k = i & 127;
        float v;
        if (n < 512) v = Wq[k * 512 + n];
        else if (n < 1536) v = Wkv[k * 1024 + (n - 512)];
        else v = Wsk[k * 128 + (n - 1536)];
        g_WT[(size_t)n * 128 + k] = __float2half(v);
    }
    if (i < 128 * 128) {
        int n = i >> 7, k = i & 127;
        g_WsqT[(size_t)n * 128 + k] = __float2half(Wsq[k * 128 + n]);
    }
    if (i < 128 * 512) {
        int n = i >> 9, k = i & 511;
        g_WoT[(size_t)n * 512 + k] = __float2half(Wo[k * 128 + n]);
    }
    if (i < 1664) g_bias1664[i] = (i < 1536) ? 0.f : bsk[i - 1536];
}

// ---------------------------------------------------------------------------
// Row softmax weights: w[i,h,r] = softmax_r( sq[i,h,:].sk[r,i,h,:] / 4 )
// 256 threads = 4 (i,h) groups of 64 (one per r)
// ---------------------------------------------------------------------------
__global__ __launch_bounds__(256) void wsoft_kernel()
{
    const int g = threadIdx.x >> 6, r = threadIdx.x & 63;
    const int ih = blockIdx.x * 4 + g;         // i*8+h
    const int i = ih >> 3, h = ih & 7;
    __shared__ float sm[4][64];
    const __half* sqv = g_sqh + (size_t)i * 128 + h * 16;
    const __half* skv = g_proj + ((size_t)(r * 512 + i)) * 1664 + 1536 + h * 16;
    float dot = 0.f;
#pragma unroll
    for (int d = 0; d < 16; d++)
        dot += __half2float(sqv[d]) * __half2float(skv[d]);
    float logit = dot * 0.25f;
    sm[g][r] = logit;
    __syncthreads();
    float mx = -1e30f;
#pragma unroll 8
    for (int t = 0; t < 64; t++) mx = fmaxf(mx, sm[g][t]);
    __syncthreads();
    float e = __expf(logit - mx);
    sm[g][r] = e;
    __syncthreads();
    float sum = 0.f;
#pragma unroll 8
    for (int t = 0; t < 64; t++) sum += sm[g][t];
    g_w[(size_t)ih * 64 + r] = e / sum;
}

// ---------------------------------------------------------------------------
// Build dots operands: A = w*q  -> [h][i][(r,d)],  B = k -> [h][j][(r,d)]
// ---------------------------------------------------------------------------
__global__ __launch_bounds__(256) void prep_ab_kernel()
{
    unsigned u = blockIdx.x * 256 + threadIdx.x;  // (h,i,r,dseg)
    int dseg = u & 7;
    int r = (u >> 3) & 63;
    int i = (u >> 9) & 511;
    int h = u >> 18;
    size_t src = ((size_t)(r * 512 + i)) * 1664 + h * 64 + dseg * 8;
    uint4 qv = *(const uint4*)(g_proj + src);
    float w = g_w[((size_t)i * 8 + h) * 64 + r];
    __half2* hp = (__half2*)&qv;
#pragma unroll
    for (int t = 0; t < 4; t++) {
        float2 f = __half22float2(hp[t]);
        hp[t] = __floats2half2_rn(f.x * w, f.y * w);
    }
    size_t dst = ((size_t)(h * 512 + i)) * 4096 + r * 64 + dseg * 8;
    *(uint4*)(g_Awq + dst) = qv;
    *(uint4*)(g_Bk + dst) = *(const uint4*)(g_proj + src + 512);
}

// ---------------------------------------------------------------------------
// v transpose: g_Bv[h][(r*64+d)][j] from g_proj v columns.  grid(4 jtiles, 512 z)
// ---------------------------------------------------------------------------
__global__ __launch_bounds__(256) void vtrans_kernel()
{
    const int jt = blockIdx.x, z = blockIdx.y;
    const int r = z >> 3, h = z & 7;
    __shared__ __half ts[128][72];
    const int tid = threadIdx.x;
#pragma unroll
    for (int p = 0; p < 4; p++) {
        int u = tid + p * 256;
        int j = u >> 3, dseg = u & 7;
        uint4 v = *(const uint4*)(g_proj +
            ((size_t)(r * 512 + jt * 128 + j)) * 1664 + 1024 + h * 64 + dseg * 8);
        *(uint4*)&ts[j][dseg * 8] = v;
    }
    __syncthreads();
#pragma unroll
    for (int p = 0; p < 4; p++) {
        int u = tid + p * 256;
        int d = u & 63, jseg = u >> 6;
        __half tmp[8];
#pragma unroll
        for (int jj = 0; jj < 8; jj++) tmp[jj] = ts[jseg * 8 + jj][d];
        *(uint4*)(g_Bv + (size_t)h * (4096 * 512)
                  + ((size_t)(r * 64 + d)) * 512 + jt * 128 + jseg * 8) =
            *(uint4*)tmp;
    }
}

// ---------------------------------------------------------------------------
// Pair bias: dots[h][i][j] = LN(pair[i,j,:]) @ Wpair[:,h]  (initializes g_dots)
// ---------------------------------------------------------------------------
__global__ __launch_bounds__(256) void pb_kernel(
    const float* __restrict__ pair, const float* __restrict__ ln_g,
    const float* __restrict__ ln_b, const float* __restrict__ Wpair)
{
    const int i = blockIdx.x;
    const int warp = threadIdx.x >> 5;
    const int lane = threadIdx.x & 31;
    const int j = blockIdx.y * 8 + warp;
    const float* p = pair + ((size_t)i * 512 + j) * 128;
    float xv[4];
#pragma unroll
    for (int t = 0; t < 4; t++) xv[t] = p[lane + 32 * t];
    float s  = xv[0] + xv[1] + xv[2] + xv[3];
    float s2 = xv[0]*xv[0] + xv[1]*xv[1] + xv[2]*xv[2] + xv[3]*xv[3];
#pragma unroll
    for (int o = 16; o > 0; o >>= 1) {
        s  += __shfl_xor_sync(0xffffffffu, s,  o);
        s2 += __shfl_xor_sync(0xffffffffu, s2, o);
    }
    const float mu  = s * (1.f / 128.f);
    const float var = s2 * (1.f / 128.f) - mu * mu;
    const float inv = rsqrtf(var + 1e-5f);
    float y[4];
#pragma unroll
    for (int t = 0; t < 4; t++) {
        int c = lane + 32 * t;
        y[t] = (xv[t] - mu) * inv * ln_g[c] + ln_b[c];
    }
    float accs[8];
#pragma unroll
    for (int h = 0; h < 8; h++) {
        float a = 0.f;
#pragma unroll
        for (int t = 0; t < 4; t++) {
            int c = lane + 32 * t;
            a += y[t] * Wpair[c * 8 + h];
        }
#pragma unroll
        for (int o = 16; o > 0; o >>= 1) a += __shfl_xor_sync(0xffffffffu, a, o);
        accs[h] = a;
    }
    if (lane < 8)
        g_dots[((size_t)lane * 512 + i) * 512 + j] = accs[lane];
}

// ---------------------------------------------------------------------------
// Softmax over j: sum pair bias + 4 K-split partials, write fp16 attn
// ---------------------------------------------------------------------------
__global__ __launch_bounds__(256) void softj_kernel()
{
    const size_t off = (size_t)blockIdx.x * 512;
    __half* orow = g_attnh + off;
    __shared__ float red[256];
    const int t = threadIdx.x;
    float v0 = g_dots[off + t] + g_dots4[off + t]
             + g_dots4[DOTS_SLICE + off + t]
             + g_dots4[2 * DOTS_SLICE + off + t]
             + g_dots4[3 * DOTS_SLICE + off + t];
    float v1 = g_dots[off + t + 256] + g_dots4[off + t + 256]
             + g_dots4[DOTS_SLICE + off + t + 256]
             + g_dots4[2 * DOTS_SLICE + off + t + 256]
             + g_dots4[3 * DOTS_SLICE + off + t + 256];
    red[t] = fmaxf(v0, v1);
    __syncthreads();
#pragma unroll
    for (int o = 128; o > 0; o >>= 1) {
        if (t < o) red[t] = fmaxf(red[t], red[t + o]);
        __syncthreads();
    }
    const float mx = red[0];
    __syncthreads();
    float e0 = __expf(v0 - mx), e1 = __expf(v1 - mx);
    red[t] = e0 + e1;
    __syncthreads();
#pragma unroll
    for (int o = 128; o > 0; o >>= 1) {
        if (t < o) red[t] = red[t] + red[t + o];
        __syncthreads();
    }
    const float inv = 1.f / red[0];
    orow[t] = __float2half(e0 * inv);
    orow[t + 256] = __float2half(e1 * inv);
}

// ---------------------------------------------------------------------------
extern "C" void kernel_launch(void* const* d_in, const int* in_sizes, int n_in,
                              void* d_out, int out_size)
{
    const float* x     = (const float*)d_in[0];
    const float* pair  = (const float*)d_in[1];
    const float* Wq    = (const float*)d_in[2];
    const float* Wkv   = (const float*)d_in[3];
    const float* Wo    = (const float*)d_in[4];
    const float* bo    = (const float*)d_in[5];
    const float* ln_g  = (const float*)d_in[6];
    const float* ln_b  = (const float*)d_in[7];
    const float* Wpair = (const float*)d_in[8];
    const float* Wsq   = (const float*)d_in[9];
    const float* bsq   = (const float*)d_in[10];
    const float* Wsk   = (const float*)d_in[11];
    const float* bsk   = (const float*)d_in[12];
    float* out = (float*)d_out;

    __half *p_xh, *p_WT, *p_WsqT, *p_WoT, *p_proj, *p_sqh, *p_Awq, *p_Bk, *p_Bv,
           *p_attnh, *p_oattnh;
    float *p_bias1664, *p_dots4;
    cudaGetSymbolAddress((void**)&p_xh, g_xh);
    cudaGetSymbolAddress((void**)&p_WT, g_WT);
    cudaGetSymbolAddress((void**)&p_WsqT, g_WsqT);
    cudaGetSymbolAddress((void**)&p_WoT, g_WoT);
    cudaGetSymbolAddress((void**)&p_proj, g_proj);
    cudaGetSymbolAddress((void**)&p_sqh, g_sqh);
    cudaGetSymbolAddress((void**)&p_Awq, g_Awq);
    cudaGetSymbolAddress((void**)&p_Bk, g_Bk);
    cudaGetSymbolAddress((void**)&p_Bv, g_Bv);
    cudaGetSymbolAddress((void**)&p_attnh, g_attnh);
    cudaGetSymbolAddress((void**)&p_oattnh, g_oattnh);
    cudaGetSymbolAddress((void**)&p_bias1664, g_bias1664);
    cudaGetSymbolAddress((void**)&p_dots4, g_dots4);

    const int SMEM = 3 * (128 + 128) * 40 * 2;   // 61440 B
    cudaFuncSetAttribute(mma_nt<1, 0>, cudaFuncAttributeMaxDynamicSharedMemorySize, SMEM);
    cudaFuncSetAttribute(mma_nt<2, 0>, cudaFuncAttributeMaxDynamicSharedMemorySize, SMEM);
    cudaFuncSetAttribute(mma_nt<3, 2>, cudaFuncAttributeMaxDynamicSharedMemorySize, SMEM);
    cudaFuncSetAttribute(mma_nt<4, 0>, cudaFuncAttributeMaxDynamicSharedMemorySize, SMEM);

    // prep
    build_wb_kernel<<<832, 256>>>(Wq, Wkv, Wsk, Wsq, Wo, bsk);
    cvt_x_kernel<<<4096, 256>>>(x);
    // pair bias (fp32) -> g_dots
    pb_kernel<<<dim3(512, 64), 256>>>(pair, ln_g, ln_b, Wpair);
    // fused projection: [q|k|v|sk] = x @ WT^T  (M=32768, N=1664, K=128)
    mma_nt<1, 0><<<dim3(13, 256, 1), 256, SMEM>>>(
        p_xh, p_WT, nullptr, p_proj, p_bias1664, 128, 128, 128, 1664, 0, 0, 0, 1.f);
    // sq = x[:512] @ Wsq^T + bsq
    mma_nt<1, 0><<<dim3(1, 4, 1), 256, SMEM>>>(
        p_xh, p_WsqT, nullptr, p_sqh, bsq, 128, 128, 128, 128, 0, 0, 0, 1.f);
    // tied-row softmax weights
    wsoft_kernel<<<1024, 256>>>();
    // dots operands (w*q scatter, k scatter)
    prep_ab_kernel<<<8192, 256>>>();
    // v transpose -> [h][(r,d)][j]
    vtrans_kernel<<<dim3(4, 512), 256>>>();
    // dots partials: 0.125 * (wq) @ k^T per (h, ksplit): M=512,N=512,K=1024,Z=32
    mma_nt<3, 2><<<dim3(4, 4, 32), 256, SMEM>>>(
        p_Awq, p_Bk, p_dots4, nullptr, nullptr, 1024, 4096, 4096, 512,
        (long)512 * 4096, (long)512 * 4096, (long)512 * 512, 0.125f);
    // softmax over j (sums partials) -> fp16 attn
    softj_kernel<<<4096, 256>>>();
    // out_attn = attn @ v per h: M=512, N=4096, K=512, Z=8, scatter epilogue
    mma_nt<4, 0><<<dim3(32, 4, 8), 256, SMEM>>>(
        p_attnh, p_Bv, nullptr, p_oattnh, nullptr, 512, 512, 512, 0,
        (long)512 * 512, (long)4096 * 512, 0, 1.f);
    // final: out = oattn @ Wo^T + bo  (M=32768, N=128, K=512)
    mma_nt<2, 0><<<dim3(1, 256, 1), 256, SMEM>>>(
        p_oattnh, p_WoT, out, nullptr, bo, 512, 512, 512, 128, 0, 0, 0, 1.f);
}